// round 13
// baseline (speedup 1.0000x reference)
#include <cuda_runtime.h>
#include <math.h>

#define B      4096
#define NSUB   20
#define NNEG   5
#define DIM    128
#define NWARPS 4                       // warps (batch elements) per block
#define GRID   (B / NWARPS)            // 1024 blocks

__device__ float    g_partial[GRID];
__device__ unsigned g_done = 0;

__device__ __forceinline__ float log_sigmoid_f(float x) {
    return fminf(x, 0.0f) - log1pf(expf(-fabsf(x)));
}

__device__ __forceinline__ float4 ldcg_f4(const float4* p) {
    return __ldcg(p);                  // skip L1 allocate, keep L2
}

__global__ __launch_bounds__(NWARPS * 32)
void fasttext_fused_kernel(const int* __restrict__ u_pos,
                           const int* __restrict__ v_pos,
                           const int* __restrict__ v_neg,
                           const float* __restrict__ uw,
                           const float* __restrict__ vw,
                           float* __restrict__ out) {
    const int lane = threadIdx.x & 31;
    const int warp = threadIdx.x >> 5;
    const int b    = blockIdx.x * NWARPS + warp;   // batch element for this warp

    // ---- stage indices into registers (lane-strided), broadcast via shfl ----
    // (register staging is load-bearing: all gather addresses are ready at
    //  loop entry so ptxas front-batches the LDG.128 stream)
    int iu = 0, iv = 0;
    if (lane < NSUB) {
        iu = u_pos[b * NSUB + lane];
        iv = v_pos[b * NSUB + lane];
    }
    int in0, in1, in2, in3 = 0;
    {
        const int base = b * NSUB * NNEG;
        in0 = v_neg[base + lane];
        in1 = v_neg[base + 32 + lane];
        in2 = v_neg[base + 64 + lane];
        if (lane < 4) in3 = v_neg[base + 96 + lane];
    }

    // 32-bit byte-offset addressing: tables are 512 MB (< 4 GB), row = 512 B.
    const char* uwB = (const char*)uw;
    const char* vwB = (const char*)vw;
    const unsigned laneOff = (unsigned)lane * 16u;

    float4 ua = make_float4(0.f, 0.f, 0.f, 0.f);
    float4 va = make_float4(0.f, 0.f, 0.f, 0.f);

    #pragma unroll
    for (int s = 0; s < NSUB; ++s) {
        const unsigned idx_u = (unsigned)__shfl_sync(0xFFFFFFFFu, iu, s);
        const unsigned idx_v = (unsigned)__shfl_sync(0xFFFFFFFFu, iv, s);
        if (idx_u != 0u) {                   // padding_idx = 0
            float4 r = ldcg_f4((const float4*)(uwB + (idx_u << 9) + laneOff));
            ua.x += r.x; ua.y += r.y; ua.z += r.z; ua.w += r.w;
        }
        float4 r = ldcg_f4((const float4*)(vwB + (idx_v << 9) + laneOff));
        va.x += r.x; va.y += r.y; va.z += r.z; va.w += r.w;
    }

    float4 na[NNEG];
    #pragma unroll
    for (int n = 0; n < NNEG; ++n) na[n] = make_float4(0.f, 0.f, 0.f, 0.f);

    // layout [NSUB, NNEG]: j = s*NNEG + n  ->  accumulator n = j % NNEG
    #pragma unroll
    for (int j = 0; j < NSUB * NNEG; ++j) {
        int srcI;
        if      (j < 32) srcI = __shfl_sync(0xFFFFFFFFu, in0, j);
        else if (j < 64) srcI = __shfl_sync(0xFFFFFFFFu, in1, j - 32);
        else if (j < 96) srcI = __shfl_sync(0xFFFFFFFFu, in2, j - 64);
        else             srcI = __shfl_sync(0xFFFFFFFFu, in3, j - 96);
        const unsigned src = (unsigned)srcI;
        float4 r = ldcg_f4((const float4*)(vwB + (src << 9) + laneOff));
        const int n = j % NNEG;
        na[n].x += r.x; na[n].y += r.y; na[n].z += r.z; na[n].w += r.w;
    }

    // ---- six dot products, warp-reduced ----
    float p[1 + NNEG];
    p[0] = ua.x * va.x + ua.y * va.y + ua.z * va.z + ua.w * va.w;
    #pragma unroll
    for (int n = 0; n < NNEG; ++n)
        p[1 + n] = ua.x * na[n].x + ua.y * na[n].y + ua.z * na[n].z + ua.w * na[n].w;

    #pragma unroll
    for (int i = 0; i < 1 + NNEG; ++i) {
        #pragma unroll
        for (int off = 16; off > 0; off >>= 1)
            p[i] += __shfl_xor_sync(0xFFFFFFFFu, p[i], off);
    }

    __shared__ float s_loss[NWARPS];
    if (lane == 0) {
        const float inv_ns2 = 1.0f / (float)(NSUB * NSUB);
        float loss = log_sigmoid_f(p[0] * inv_ns2);
        #pragma unroll
        for (int n = 0; n < NNEG; ++n)
            loss += log_sigmoid_f(-(p[1 + n] * inv_ns2));
        s_loss[warp] = loss;
    }
    __syncthreads();

    // ---- per-block partial, then last-block deterministic final reduce ----
    __shared__ bool s_last;
    if (threadIdx.x == 0) {
        g_partial[blockIdx.x] = s_loss[0] + s_loss[1] + s_loss[2] + s_loss[3];
        __threadfence();
        unsigned prev = atomicAdd(&g_done, 1u);
        s_last = (prev == GRID - 1);
    }
    __syncthreads();

    if (s_last) {
        __threadfence();
        const int t = threadIdx.x;               // 128 threads
        float a = 0.0f;
        #pragma unroll
        for (int k = 0; k < GRID / 128; ++k)     // fixed order: deterministic
            a += *((volatile float*)&g_partial[t + k * 128]);
        __shared__ float red[128];
        red[t] = a;
        __syncthreads();
        #pragma unroll
        for (int off = 64; off > 0; off >>= 1) {
            if (t < off) red[t] += red[t + off];
            __syncthreads();
        }
        if (t == 0) {
            out[0] = -red[0] / (float)B;
            g_done = 0;                          // reset for next graph replay
        }
    }
}

extern "C" void kernel_launch(void* const* d_in, const int* in_sizes, int n_in,
                              void* d_out, int out_size) {
    // metadata order: u_pos, v_pos, v_neg, batch_size, u_weight, v_weight
    const int*   u_pos = (const int*)d_in[0];
    const int*   v_pos = (const int*)d_in[1];
    const int*   v_neg = (const int*)d_in[2];
    const float* uw    = (const float*)d_in[4];
    const float* vw    = (const float*)d_in[5];
    float* out = (float*)d_out;

    fasttext_fused_kernel<<<GRID, NWARPS * 32>>>(u_pos, v_pos, v_neg, uw, vw, out);
}

// round 14
// speedup vs baseline: 1.0269x; 1.0269x over previous
#include <cuda_runtime.h>
#include <math.h>

#define B      4096
#define NSUB   20
#define NNEG   5
#define DIM    128
#define NWARPS 4                       // warps (batch elements) per block
#define GRID   (B / NWARPS)            // 1024 blocks

__device__ float    g_partial[GRID];
__device__ unsigned g_done = 0;

__device__ __forceinline__ float log_sigmoid_f(float x) {
    return fminf(x, 0.0f) - log1pf(expf(-fabsf(x)));
}

__device__ __forceinline__ float4 ldcg_f4(const float4* p) {
    return __ldcg(p);                  // skip L1 allocate, keep L2
}

__global__ __launch_bounds__(NWARPS * 32)
void fasttext_fused_kernel(const int* __restrict__ u_pos,
                           const int* __restrict__ v_pos,
                           const int* __restrict__ v_neg,
                           const float* __restrict__ uw,
                           const float* __restrict__ vw,
                           float* __restrict__ out) {
    const int lane = threadIdx.x & 31;
    const int warp = threadIdx.x >> 5;
    const int b    = blockIdx.x * NWARPS + warp;   // batch element for this warp

    // ---- stage indices into registers (lane-strided), broadcast via shfl ----
    int iu = 0, iv = 0;
    if (lane < NSUB) {
        iu = u_pos[b * NSUB + lane];
        iv = v_pos[b * NSUB + lane];
    }
    int in0, in1, in2, in3 = 0;
    {
        const int base = b * NSUB * NNEG;
        in0 = v_neg[base + lane];
        in1 = v_neg[base + 32 + lane];
        in2 = v_neg[base + 64 + lane];
        if (lane < 4) in3 = v_neg[base + 96 + lane];
    }

    // 32-bit byte-offset addressing: tables are 512 MB (< 4 GB), row = 512 B.
    const char* uwB = (const char*)uw;
    const char* vwB = (const char*)vw;
    const unsigned laneOff = (unsigned)lane * 16u;

    float4 ua = make_float4(0.f, 0.f, 0.f, 0.f);
    float4 va = make_float4(0.f, 0.f, 0.f, 0.f);
    float4 na[NNEG];
    #pragma unroll
    for (int n = 0; n < NNEG; ++n) na[n] = make_float4(0.f, 0.f, 0.f, 0.f);

    // ---- single interleaved gather stream: 7 rows per s-iteration ----
    // (keeps the conditional u-load — R8 showed unconditional+mask inflates
    //  registers; this isolates the merge itself)
    #pragma unroll
    for (int s = 0; s < NSUB; ++s) {
        const unsigned idx_u = (unsigned)__shfl_sync(0xFFFFFFFFu, iu, s);
        const unsigned idx_v = (unsigned)__shfl_sync(0xFFFFFFFFu, iv, s);
        if (idx_u != 0u) {                   // padding_idx = 0
            float4 r = ldcg_f4((const float4*)(uwB + (idx_u << 9) + laneOff));
            ua.x += r.x; ua.y += r.y; ua.z += r.z; ua.w += r.w;
        }
        {
            float4 r = ldcg_f4((const float4*)(vwB + (idx_v << 9) + laneOff));
            va.x += r.x; va.y += r.y; va.z += r.z; va.w += r.w;
        }
        // 5 neg rows for this s: j = s*NNEG + q, accumulator q
        #pragma unroll
        for (int q = 0; q < NNEG; ++q) {
            const int j = s * NNEG + q;
            int srcI;
            if      (j < 32) srcI = __shfl_sync(0xFFFFFFFFu, in0, j);
            else if (j < 64) srcI = __shfl_sync(0xFFFFFFFFu, in1, j - 32);
            else if (j < 96) srcI = __shfl_sync(0xFFFFFFFFu, in2, j - 64);
            else             srcI = __shfl_sync(0xFFFFFFFFu, in3, j - 96);
            const unsigned src = (unsigned)srcI;
            float4 r = ldcg_f4((const float4*)(vwB + (src << 9) + laneOff));
            na[q].x += r.x; na[q].y += r.y; na[q].z += r.z; na[q].w += r.w;
        }
    }

    // ---- six dot products, warp-reduced ----
    float p[1 + NNEG];
    p[0] = ua.x * va.x + ua.y * va.y + ua.z * va.z + ua.w * va.w;
    #pragma unroll
    for (int n = 0; n < NNEG; ++n)
        p[1 + n] = ua.x * na[n].x + ua.y * na[n].y + ua.z * na[n].z + ua.w * na[n].w;

    #pragma unroll
    for (int i = 0; i < 1 + NNEG; ++i) {
        #pragma unroll
        for (int off = 16; off > 0; off >>= 1)
            p[i] += __shfl_xor_sync(0xFFFFFFFFu, p[i], off);
    }

    __shared__ float s_loss[NWARPS];
    if (lane == 0) {
        const float inv_ns2 = 1.0f / (float)(NSUB * NSUB);
        float loss = log_sigmoid_f(p[0] * inv_ns2);
        #pragma unroll
        for (int n = 0; n < NNEG; ++n)
            loss += log_sigmoid_f(-(p[1 + n] * inv_ns2));
        s_loss[warp] = loss;
    }
    __syncthreads();

    // ---- per-block partial, then last-block deterministic final reduce ----
    __shared__ bool s_last;
    if (threadIdx.x == 0) {
        g_partial[blockIdx.x] = s_loss[0] + s_loss[1] + s_loss[2] + s_loss[3];
        __threadfence();
        unsigned prev = atomicAdd(&g_done, 1u);
        s_last = (prev == GRID - 1);
    }
    __syncthreads();

    if (s_last) {
        __threadfence();
        const int t = threadIdx.x;               // 128 threads
        float a = 0.0f;
        #pragma unroll
        for (int k = 0; k < GRID / 128; ++k)     // fixed order: deterministic
            a += *((volatile float*)&g_partial[t + k * 128]);
        __shared__ float red[128];
        red[t] = a;
        __syncthreads();
        #pragma unroll
        for (int off = 64; off > 0; off >>= 1) {
            if (t < off) red[t] += red[t + off];
            __syncthreads();
        }
        if (t == 0) {
            out[0] = -red[0] / (float)B;
            g_done = 0;                          // reset for next graph replay
        }
    }
}

extern "C" void kernel_launch(void* const* d_in, const int* in_sizes, int n_in,
                              void* d_out, int out_size) {
    // metadata order: u_pos, v_pos, v_neg, batch_size, u_weight, v_weight
    const int*   u_pos = (const int*)d_in[0];
    const int*   v_pos = (const int*)d_in[1];
    const int*   v_neg = (const int*)d_in[2];
    const float* uw    = (const float*)d_in[4];
    const float* vw    = (const float*)d_in[5];
    float* out = (float*)d_out;

    fasttext_fused_kernel<<<GRID, NWARPS * 32>>>(u_pos, v_pos, v_neg, uw, vw, out);
}

// round 15
// speedup vs baseline: 1.0303x; 1.0034x over previous
#include <cuda_runtime.h>
#include <math.h>

#define B      4096
#define NSUB   20
#define NNEG   5
#define DIM    128
#define NWARPS 4                       // warps (batch elements) per block
#define GRID   (B / NWARPS)            // 1024 blocks

__device__ float    g_partial[GRID];
__device__ unsigned g_done = 0;

__device__ __forceinline__ float log_sigmoid_f(float x) {
    return fminf(x, 0.0f) - log1pf(expf(-fabsf(x)));
}

__device__ __forceinline__ float4 ldcg_f4(const float4* p) {
    return __ldcg(p);                  // skip L1 allocate, keep L2
}

__global__ __launch_bounds__(NWARPS * 32)
void fasttext_fused_kernel(const int* __restrict__ u_pos,
                           const int* __restrict__ v_pos,
                           const int* __restrict__ v_neg,
                           const float* __restrict__ uw,
                           const float* __restrict__ vw,
                           float* __restrict__ out) {
    const int lane = threadIdx.x & 31;
    const int warp = threadIdx.x >> 5;
    const int b    = blockIdx.x * NWARPS + warp;   // batch element for this warp

    // ---- stage indices into registers (lane-strided), broadcast via shfl ----
    // (register staging is load-bearing: all gather addresses are ready at
    //  loop entry so ptxas front-batches the LDG.128 stream)
    int iu = 0, iv = 0;
    if (lane < NSUB) {
        iu = u_pos[b * NSUB + lane];
        iv = v_pos[b * NSUB + lane];
    }
    int in0, in1, in2, in3 = 0;
    {
        const int base = b * NSUB * NNEG;
        in0 = v_neg[base + lane];
        in1 = v_neg[base + 32 + lane];
        in2 = v_neg[base + 64 + lane];
        if (lane < 4) in3 = v_neg[base + 96 + lane];
    }

    // 32-bit byte-offset addressing: tables are 512 MB (< 4 GB), row = 512 B.
    const char* uwB = (const char*)uw;
    const char* vwB = (const char*)vw;
    const unsigned laneOff = (unsigned)lane * 16u;

    float4 ua = make_float4(0.f, 0.f, 0.f, 0.f);
    float4 va = make_float4(0.f, 0.f, 0.f, 0.f);

    #pragma unroll
    for (int s = 0; s < NSUB; ++s) {
        const unsigned idx_u = (unsigned)__shfl_sync(0xFFFFFFFFu, iu, s);
        const unsigned idx_v = (unsigned)__shfl_sync(0xFFFFFFFFu, iv, s);
        if (idx_u != 0u) {                   // padding_idx = 0
            float4 r = ldcg_f4((const float4*)(uwB + (idx_u << 9) + laneOff));
            ua.x += r.x; ua.y += r.y; ua.z += r.z; ua.w += r.w;
        }
        float4 r = ldcg_f4((const float4*)(vwB + (idx_v << 9) + laneOff));
        va.x += r.x; va.y += r.y; va.z += r.z; va.w += r.w;
    }

    float4 na[NNEG];
    #pragma unroll
    for (int n = 0; n < NNEG; ++n) na[n] = make_float4(0.f, 0.f, 0.f, 0.f);

    // layout [NSUB, NNEG]: j = s*NNEG + n  ->  accumulator n = j % NNEG
    #pragma unroll
    for (int j = 0; j < NSUB * NNEG; ++j) {
        int srcI;
        if      (j < 32) srcI = __shfl_sync(0xFFFFFFFFu, in0, j);
        else if (j < 64) srcI = __shfl_sync(0xFFFFFFFFu, in1, j - 32);
        else if (j < 96) srcI = __shfl_sync(0xFFFFFFFFu, in2, j - 64);
        else             srcI = __shfl_sync(0xFFFFFFFFu, in3, j - 96);
        const unsigned src = (unsigned)srcI;
        float4 r = ldcg_f4((const float4*)(vwB + (src << 9) + laneOff));
        const int n = j % NNEG;
        na[n].x += r.x; na[n].y += r.y; na[n].z += r.z; na[n].w += r.w;
    }

    // ---- six dot products, warp-reduced ----
    float p[1 + NNEG];
    p[0] = ua.x * va.x + ua.y * va.y + ua.z * va.z + ua.w * va.w;
    #pragma unroll
    for (int n = 0; n < NNEG; ++n)
        p[1 + n] = ua.x * na[n].x + ua.y * na[n].y + ua.z * na[n].z + ua.w * na[n].w;

    #pragma unroll
    for (int i = 0; i < 1 + NNEG; ++i) {
        #pragma unroll
        for (int off = 16; off > 0; off >>= 1)
            p[i] += __shfl_xor_sync(0xFFFFFFFFu, p[i], off);
    }

    __shared__ float s_loss[NWARPS];
    if (lane == 0) {
        const float inv_ns2 = 1.0f / (float)(NSUB * NSUB);
        float loss = log_sigmoid_f(p[0] * inv_ns2);
        #pragma unroll
        for (int n = 0; n < NNEG; ++n)
            loss += log_sigmoid_f(-(p[1 + n] * inv_ns2));
        s_loss[warp] = loss;
    }
    __syncthreads();

    // ---- per-block partial, then last-block deterministic final reduce ----
    __shared__ bool s_last;
    if (threadIdx.x == 0) {
        g_partial[blockIdx.x] = s_loss[0] + s_loss[1] + s_loss[2] + s_loss[3];
        __threadfence();
        unsigned prev = atomicAdd(&g_done, 1u);
        s_last = (prev == GRID - 1);
    }
    __syncthreads();

    if (s_last) {
        __threadfence();
        const int t = threadIdx.x;               // 128 threads
        float a = 0.0f;
        #pragma unroll
        for (int k = 0; k < GRID / 128; ++k)     // fixed order: deterministic
            a += *((volatile float*)&g_partial[t + k * 128]);
        __shared__ float red[128];
        red[t] = a;
        __syncthreads();
        #pragma unroll
        for (int off = 64; off > 0; off >>= 1) {
            if (t < off) red[t] += red[t + off];
            __syncthreads();
        }
        if (t == 0) {
            out[0] = -red[0] / (float)B;
            g_done = 0;                          // reset for next graph replay
        }
    }
}

extern "C" void kernel_launch(void* const* d_in, const int* in_sizes, int n_in,
                              void* d_out, int out_size) {
    // metadata order: u_pos, v_pos, v_neg, batch_size, u_weight, v_weight
    const int*   u_pos = (const int*)d_in[0];
    const int*   v_pos = (const int*)d_in[1];
    const int*   v_neg = (const int*)d_in[2];
    const float* uw    = (const float*)d_in[4];
    const float* vw    = (const float*)d_in[5];
    float* out = (float*)d_out;

    fasttext_fused_kernel<<<GRID, NWARPS * 32>>>(u_pos, v_pos, v_neg, uw, vw, out);
}